// round 17
// baseline (speedup 1.0000x reference)
#include <cuda_runtime.h>
#include <cstdint>

#define N_NODES 100000
#define N_EDGES 3200000
#define E4 (N_EDGES / 4)

// Scratch (device globals — zero-initialized at module load; no allocation).
__device__ float  g_deg[N_NODES];    // consume-and-reset each replay
__device__ float  g_dinv[N_NODES];
__device__ float2 g_xs[N_NODES];     // x[i] * dinv[i]
__device__ float2 g_agg1[N_NODES];
__device__ float2 g_ps[N_NODES];     // (h1@W2)[i] * dinv[i]
__device__ float2 g_agg2[N_NODES];

__device__ __forceinline__ void red_add_f2(float2* addr, float2 v) {
    asm volatile("red.global.add.v2.f32 [%0], {%1, %2};"
                 :: "l"(addr), "f"(v.x), "f"(v.y) : "memory");
}
__device__ __forceinline__ void red_add_f(float* addr, float v) {
    asm volatile("red.global.add.f32 [%0], %1;"
                 :: "l"(addr), "f"(v) : "memory");
}

// ---------------------------------------------------------------------------
// PDL: trigger at block top; ALL independent loads + address arithmetic before
// griddepsync (pre-sync prologue overlaps the predecessor's drain ramp and is
// off the critical path); dependent reads after.

__global__ void k_degree(const int4* __restrict__ dst4) {
    cudaTriggerProgrammaticLaunchCompletion();
    int t = blockIdx.x * blockDim.x + threadIdx.x;
    if (t < E4) {
        int4 d = dst4[t];                         // independent
        float* a0 = &g_deg[d.x];
        float* a1 = &g_deg[d.y];
        float* a2 = &g_deg[d.z];
        float* a3 = &g_deg[d.w];
        cudaGridDependencySynchronize();
        red_add_f(a0, 1.0f);
        red_add_f(a1, 1.0f);
        red_add_f(a2, 1.0f);
        red_add_f(a3, 1.0f);
    }
}

__global__ void k_pre1(const float2* __restrict__ x2) {
    cudaTriggerProgrammaticLaunchCompletion();
    int i = blockIdx.x * blockDim.x + threadIdx.x;
    float2 xi = make_float2(0.f, 0.f);
    if (i < N_NODES) xi = x2[i];                  // independent
    cudaGridDependencySynchronize();              // wait for k_degree
    if (i < N_NODES) {
        float dg = g_deg[i];
        g_deg[i] = 0.f;                           // reset for next replay
        float di = rsqrtf(dg + 1.0f);             // +1 self-loop
        g_dinv[i] = di;
        float2 xs = make_float2(xi.x * di, xi.y * di);
        g_xs[i]   = xs;
        g_agg1[i] = xs;                           // self-loop seed
    }
}

__global__ void k_scatter1(const int4* __restrict__ src4,
                           const int4* __restrict__ dst4) {
    cudaTriggerProgrammaticLaunchCompletion();
    int t = blockIdx.x * blockDim.x + threadIdx.x;
    if (t < E4) {
        int4 s = src4[t];                         // independent
        int4 d = dst4[t];
        const float2* p0 = &g_xs[s.x];
        const float2* p1 = &g_xs[s.y];
        const float2* p2 = &g_xs[s.z];
        const float2* p3 = &g_xs[s.w];
        float2* q0 = &g_agg1[d.x];
        float2* q1 = &g_agg1[d.y];
        float2* q2 = &g_agg1[d.z];
        float2* q3 = &g_agg1[d.w];
        cudaGridDependencySynchronize();          // wait for k_pre1
        float2 v0 = __ldg(p0);
        float2 v1 = __ldg(p1);
        float2 v2 = __ldg(p2);
        float2 v3 = __ldg(p3);
        red_add_f2(q0, v0);
        red_add_f2(q1, v1);
        red_add_f2(q2, v2);
        red_add_f2(q3, v3);
    } else {
        cudaGridDependencySynchronize();
    }
}

// Weights via float4, ALL loaded pre-sync (prologue overlaps scatter1 drain;
// regs/occupancy irrelevant for this overlapped latency-bound kernel —
// measured best in R14).
__global__ void k_mid(const float4* __restrict__ W1v,   // [2,16] -> 8 float4
                      const float4* __restrict__ b1v,   // [16]   -> 4 float4
                      const float4* __restrict__ W2v) { // [16,2] -> 8 float4
    cudaTriggerProgrammaticLaunchCompletion();
    int i = blockIdx.x * blockDim.x + threadIdx.x;

    float4 w1a[4], w1b[4], bb[4], w2[8];
#pragma unroll
    for (int g = 0; g < 4; g++) {
        w1a[g] = __ldg(&W1v[g]);        // W1 row0 [4g..4g+3]
        w1b[g] = __ldg(&W1v[4 + g]);    // W1 row1 [4g..4g+3]
        bb[g]  = __ldg(&b1v[g]);
        w2[2 * g]     = __ldg(&W2v[2 * g]);      // rows j=4g,4g+1 of [16,2]
        w2[2 * g + 1] = __ldg(&W2v[2 * g + 1]);  // rows j=4g+2,4g+3
    }
    cudaGridDependencySynchronize();              // wait for k_scatter1
    if (i >= N_NODES) return;

    float di = g_dinv[i];
    float2 t = g_agg1[i];
    float ax = t.x * di, ay = t.y * di;
    float px = 0.f, py = 0.f;
#pragma unroll
    for (int g = 0; g < 4; g++) {
        float h0 = fmaxf(ax * w1a[g].x + ay * w1b[g].x + bb[g].x, 0.f);
        float h1 = fmaxf(ax * w1a[g].y + ay * w1b[g].y + bb[g].y, 0.f);
        float h2 = fmaxf(ax * w1a[g].z + ay * w1b[g].z + bb[g].z, 0.f);
        float h3 = fmaxf(ax * w1a[g].w + ay * w1b[g].w + bb[g].w, 0.f);
        px += h0 * w2[2 * g].x + h1 * w2[2 * g].z
            + h2 * w2[2 * g + 1].x + h3 * w2[2 * g + 1].z;
        py += h0 * w2[2 * g].y + h1 * w2[2 * g].w
            + h2 * w2[2 * g + 1].y + h3 * w2[2 * g + 1].w;
    }
    float2 ps = make_float2(px * di, py * di);
    g_ps[i]   = ps;
    g_agg2[i] = ps;                               // self-loop seed
}

__global__ void k_scatter2(const int4* __restrict__ src4,
                           const int4* __restrict__ dst4) {
    cudaTriggerProgrammaticLaunchCompletion();
    int t = blockIdx.x * blockDim.x + threadIdx.x;
    if (t < E4) {
        int4 s = src4[t];                         // independent
        int4 d = dst4[t];
        const float2* p0 = &g_ps[s.x];
        const float2* p1 = &g_ps[s.y];
        const float2* p2 = &g_ps[s.z];
        const float2* p3 = &g_ps[s.w];
        float2* q0 = &g_agg2[d.x];
        float2* q1 = &g_agg2[d.y];
        float2* q2 = &g_agg2[d.z];
        float2* q3 = &g_agg2[d.w];
        cudaGridDependencySynchronize();          // wait for k_mid
        float2 v0 = __ldg(p0);
        float2 v1 = __ldg(p1);
        float2 v2 = __ldg(p2);
        float2 v3 = __ldg(p3);
        red_add_f2(q0, v0);
        red_add_f2(q1, v1);
        red_add_f2(q2, v2);
        red_add_f2(q3, v3);
    } else {
        cudaGridDependencySynchronize();
    }
}

__global__ void k_out(const float* __restrict__ b2, float2* __restrict__ out2) {
    cudaTriggerProgrammaticLaunchCompletion();
    int i = blockIdx.x * blockDim.x + threadIdx.x;
    float bx = __ldg(&b2[0]), by = __ldg(&b2[1]); // independent
    cudaGridDependencySynchronize();              // wait for k_scatter2
    if (i >= N_NODES) return;
    float di = g_dinv[i];
    float2 t = g_agg2[i];
    float zx = t.x * di + bx;
    float zy = t.y * di + by;
    float m = fmaxf(zx, zy);
    float l = m + __logf(__expf(zx - m) + __expf(zy - m));
    out2[i] = make_float2(zx - l, zy - l);
}

// ---------------------------------------------------------------------------
extern "C" void kernel_launch(void* const* d_in, const int* in_sizes, int n_in,
                              void* d_out, int out_size) {
    const float* x  = (const float*)d_in[0];   // [N,2]
    const int*   ei = (const int*)d_in[1];     // [2,E] int32
    const float* W1 = (const float*)d_in[2];
    const float* b1 = (const float*)d_in[3];
    const float* W2 = (const float*)d_in[4];
    const float* b2 = (const float*)d_in[5];

    const int4* src4 = (const int4*)ei;
    const int4* dst4 = (const int4*)(ei + N_EDGES);
    const float2* x2 = (const float2*)x;
    const float4* W1v = (const float4*)W1;
    const float4* b1v = (const float4*)b1;
    const float4* W2v = (const float4*)W2;
    float2* out2 = (float2*)d_out;

    const int T = 256;
    const int gN  = (N_NODES + T - 1) / T;
    const int gE4 = (E4 + T - 1) / T;

    cudaLaunchAttribute attr;
    attr.id = cudaLaunchAttributeProgrammaticStreamSerialization;
    attr.val.programmaticStreamSerializationAllowed = 1;

    cudaLaunchConfig_t cfg = {};
    cfg.blockDim = dim3(T, 1, 1);
    cfg.dynamicSmemBytes = 0;
    cfg.stream = 0;
    cfg.attrs = &attr;
    cfg.numAttrs = 1;

    // First node: plain launch (no intra-graph predecessor).
    k_degree<<<gE4, T>>>(dst4);

    cfg.gridDim = dim3(gN, 1, 1);
    cudaLaunchKernelEx(&cfg, k_pre1, x2);

    cfg.gridDim = dim3(gE4, 1, 1);
    cudaLaunchKernelEx(&cfg, k_scatter1, src4, dst4);

    cfg.gridDim = dim3(gN, 1, 1);
    cudaLaunchKernelEx(&cfg, k_mid, W1v, b1v, W2v);

    cfg.gridDim = dim3(gE4, 1, 1);
    cudaLaunchKernelEx(&cfg, k_scatter2, src4, dst4);

    cfg.gridDim = dim3(gN, 1, 1);
    cudaLaunchKernelEx(&cfg, k_out, b2, out2);
}